// round 5
// baseline (speedup 1.0000x reference)
#include <cuda_runtime.h>

#define NPT   100
#define KNN   10
#define XS    36
#define NTHR  256

typedef unsigned long long u64;

struct Ptrs {
    const float* obs;
    const float* W0; const float* W1; const float* W2; const float* W3; const float* W4;
    const float* W5; const float* W6; const float* W7; const float* W8; const float* W9;
    const float* s[9]; const float* t[9];
};

__device__ __forceinline__ float lrelu(float v) { return fmaxf(v, 0.2f * v); }

__device__ __forceinline__ u64 pack2(float lo, float hi) {
    u64 r; asm("mov.b64 %0,{%1,%2};" : "=l"(r) : "f"(lo), "f"(hi)); return r;
}
__device__ __forceinline__ void fma2(u64& d, u64 a, u64 b) {
    asm("fma.rn.f32x2 %0,%1,%2,%0;" : "+l"(d) : "l"(a), "l"(b));
}
__device__ __forceinline__ u64 add2(u64 a, u64 b) {
    u64 r; asm("add.rn.f32x2 %0,%1,%2;" : "=l"(r) : "l"(a), "l"(b)); return r;
}
__device__ __forceinline__ void unpack2(u64 v, float& a, float& b) {
    asm("mov.b64 {%0,%1},%2;" : "=f"(a), "=f"(b) : "l"(v));
}
__device__ __forceinline__ float hsum(u64 v) { float a, b; unpack2(v, a, b); return a + b; }

__device__ __forceinline__ void ldrow(u64* r, const float* p) {
    const ulonglong2* q = (const ulonglong2*)p;
    #pragma unroll
    for (int i = 0; i < 8; ++i) { ulonglong2 v = q[i]; r[2*i] = v.x; r[2*i+1] = v.y; }
}
__device__ __forceinline__ float dot32s(const u64* a, const float* b) {
    const ulonglong2* q = (const ulonglong2*)b;
    u64 s0 = 0, s1 = 0;
    #pragma unroll
    for (int i = 0; i < 8; ++i) { ulonglong2 v = q[i]; fma2(s0, a[2*i], v.x); fma2(s1, a[2*i+1], v.y); }
    return hsum(add2(s0, s1));
}
__device__ __forceinline__ float dot32ss(const float* a, const float* b) {
    const ulonglong2* pa = (const ulonglong2*)a;
    const ulonglong2* pb = (const ulonglong2*)b;
    u64 s0 = 0, s1 = 0;
    #pragma unroll
    for (int i = 0; i < 8; ++i) {
        ulonglong2 va = pa[i], vb = pb[i];
        fma2(s0, va.x, vb.x); fma2(s1, va.y, vb.y);
    }
    return hsum(add2(s0, s1));
}

// ---------------------------------------------------------------------------
// kNN: 200 threads scan j-halves of 50 -> per-half top-10; 100 threads merge.
// ---------------------------------------------------------------------------
__device__ void knn_stage(const float* __restrict__ xsrc, float* __restrict__ xx,
                          int* __restrict__ idx, float* __restrict__ scr, int tid)
{
    if (tid < NPT) {
        xx[tid] = dot32ss(xsrc + tid * XS, xsrc + tid * XS);
    }
    __syncthreads();
    float* vbuf = scr;                    // 200*10
    int*   ibuf = (int*)(scr + 2048);     // 200*10
    if (tid < 2 * NPT) {
        const int n = tid % NPT, h = tid / NPT;
        u64 xi[16]; ldrow(xi, xsrc + n * XS);
        const float nxi = xx[n];
        float v[KNN]; int id[KNN];
        #pragma unroll
        for (int p = 0; p < KNN; ++p) { v[p] = -3.4e38f; id[p] = 0; }
        for (int j = h * 50; j < h * 50 + 50; ++j) {
            float d = 2.f * dot32s(xi, xsrc + j * XS) - nxi - xx[j];
            if (d > v[KNN - 1]) {
                float dv = d; int di = j;
                #pragma unroll
                for (int p = 0; p < KNN; ++p) {
                    if (dv > v[p]) {
                        float tv = v[p]; int ti = id[p];
                        v[p] = dv; id[p] = di; dv = tv; di = ti;
                    }
                }
            }
        }
        #pragma unroll
        for (int p = 0; p < KNN; ++p) { vbuf[tid * KNN + p] = v[p]; ibuf[tid * KNN + p] = id[p]; }
    }
    __syncthreads();
    if (tid < NPT) {
        const float* va = vbuf + tid * KNN; const float* vb = vbuf + (tid + NPT) * KNN;
        const int*   ia = ibuf + tid * KNN; const int*   ib = ibuf + (tid + NPT) * KNN;
        int pa = 0, pb = 0;
        #pragma unroll
        for (int p = 0; p < KNN; ++p) {
            bool ta = va[pa] >= vb[pb];
            idx[tid * KNN + p] = ta ? ia[pa] : ib[pb];
            if (ta) ++pa; else ++pb;
        }
    }
    __syncthreads();
}

// ---------------------------------------------------------------------------
// Dual-conv EdgeConv with U/V factoring:
//   U'[j][o] = sa[o]*(Wa[o].x_j)          (100x32, per-point, stride 33)
//   V'[n][o] = sa[o]*(Wd[o].x_n) + ta[o]  (100x32, per-point, stride 36)
//   y1(e=(n,j))[o] = lrelu(U'[j][o] + V'[n][o])   (per-edge, cheap)
//   z = Wbt.y1 ; out = lrelu(sb*max_k z + tb)
// ---------------------------------------------------------------------------
__device__ void edge_dual(const float* __restrict__ xsrc, float* __restrict__ dest,
                          const int* __restrict__ idx,
                          const float* __restrict__ Wg, const float* __restrict__ Wbg,
                          const float* __restrict__ sa, const float* __restrict__ ta,
                          const float* __restrict__ sb, const float* __restrict__ tb,
                          float* __restrict__ scr,
                          float* __restrict__ pmA, float* __restrict__ pmB, int tid)
{
    float* Wa  = scr;             // 1024
    float* Wd  = scr + 1024;      // 1024
    float* Wbt = scr + 2048;      // 1024
    float* U   = scr + 3072;      // 100*33 = 3300
    float* V   = scr + 6372;      // 100*36 = 3600 (16B-aligned rows)
    for (int i = tid; i < 1024; i += NTHR) {
        int o = i >> 5, c = i & 31;
        float wa = Wg[o * 64 + c];
        Wa[i] = wa;
        Wd[i] = Wg[o * 64 + 32 + c] - wa;
        Wbt[c * 32 + o] = Wbg[i];
    }
    __syncthreads();

    // phase 1: per-point U'/V'
    if (tid < 2 * NPT) {
        const int n = tid % NPT;
        u64 xr[16]; ldrow(xr, xsrc + n * XS);
        if (tid < NPT) {
            #pragma unroll 4
            for (int o = 0; o < 32; ++o)
                U[n * 33 + o] = sa[o] * dot32s(xr, Wa + o * 32);
        } else {
            #pragma unroll 4
            for (int o = 0; o < 32; ++o)
                V[n * 36 + o] = fmaf(sa[o], dot32s(xr, Wd + o * 32), ta[o]);
        }
    }
    __syncthreads();

    // phase 2: per-edge lrelu + second conv + max over 5 nbrs per half
    if (tid < 2 * NPT) {
        const int n = tid % NPT, kh = tid / NPT;
        u64 v[16]; ldrow(v, V + n * 36);
        u64 m[16];
        #pragma unroll
        for (int i = 0; i < 16; ++i) m[i] = pack2(-3.4e38f, -3.4e38f);
        for (int kk = 0; kk < 5; ++kk) {
            const int j = idx[n * KNN + kh * 5 + kk];
            const float* urow = U + j * 33;
            u64 z[16];
            #pragma unroll
            for (int i = 0; i < 16; ++i) z[i] = 0;
            #pragma unroll
            for (int o1 = 0; o1 < 32; ++o1) {
                float va, vb; unpack2(v[o1 >> 1], va, vb);
                const float y1 = lrelu(urow[o1] + ((o1 & 1) ? vb : va));
                const u64 y2 = pack2(y1, y1);
                const ulonglong2* wb2 = (const ulonglong2*)(Wbt + o1 * 32);
                #pragma unroll
                for (int i = 0; i < 8; ++i) { ulonglong2 w = wb2[i]; fma2(z[2*i], y2, w.x); fma2(z[2*i+1], y2, w.y); }
            }
            #pragma unroll
            for (int i = 0; i < 16; ++i) {
                float za, zb, ma, mb;
                unpack2(z[i], za, zb); unpack2(m[i], ma, mb);
                m[i] = pack2(fmaxf(ma, za), fmaxf(mb, zb));
            }
        }
        float* pr = (kh == 0 ? pmA : pmB) + n * XS;
        #pragma unroll
        for (int i = 0; i < 16; ++i) {
            float a, b; unpack2(m[i], a, b);
            pr[2*i] = a; pr[2*i+1] = b;
        }
    }
    __syncthreads();
    for (int i = tid; i < 32 * NPT; i += NTHR) {
        const int n = i >> 5, o = i & 31;
        float mv = fmaxf(pmA[n * XS + o], pmB[n * XS + o]);
        dest[n * XS + o] = lrelu(fmaf(sb[o], mv, tb[o]));
    }
    __syncthreads();
}

// ---------------------------------------------------------------------------
// Single-conv EdgeConv with U/V factoring: out[n][o] =
//   lrelu(sb*(max_k U[idx[n][k]][o] + V[n][o]) + tb). No per-edge GEMM.
// ---------------------------------------------------------------------------
__device__ void edge_single(const float* __restrict__ xsrc, float* __restrict__ dest,
                            const int* __restrict__ idx,
                            const float* __restrict__ Wg,
                            const float* __restrict__ sb, const float* __restrict__ tb,
                            float* __restrict__ scr, int tid)
{
    float* Wa = scr;             // 1024
    float* Wd = scr + 1024;      // 1024
    float* U  = scr + 3072;      // 100*33
    float* V  = scr + 6372;      // 100*33
    for (int i = tid; i < 1024; i += NTHR) {
        int o = i >> 5, c = i & 31;
        float wa = Wg[o * 64 + c];
        Wa[i] = wa;
        Wd[i] = Wg[o * 64 + 32 + c] - wa;
    }
    __syncthreads();
    if (tid < 2 * NPT) {
        const int n = tid % NPT;
        u64 xr[16]; ldrow(xr, xsrc + n * XS);
        if (tid < NPT) {
            #pragma unroll 4
            for (int o = 0; o < 32; ++o)
                U[n * 33 + o] = dot32s(xr, Wa + o * 32);
        } else {
            #pragma unroll 4
            for (int o = 0; o < 32; ++o)
                V[n * 33 + o] = dot32s(xr, Wd + o * 32);
        }
    }
    __syncthreads();
    if (tid < NPT) {
        const int n = tid;
        float m[32];
        #pragma unroll
        for (int o = 0; o < 32; ++o) m[o] = -3.4e38f;
        #pragma unroll 1
        for (int kk = 0; kk < KNN; ++kk) {
            const int j = idx[n * KNN + kk];
            const float* urow = U + j * 33;
            #pragma unroll
            for (int o = 0; o < 32; ++o) m[o] = fmaxf(m[o], urow[o]);
        }
        #pragma unroll
        for (int o = 0; o < 32; ++o)
            dest[n * XS + o] = lrelu(fmaf(sb[o], m[o] + V[n * 33 + o], tb[o]));
    }
    __syncthreads();
}

// ---------------------------------------------------------------------------
// Main fused kernel: one CTA per batch element, 256 threads, 2 CTAs/SM.
// smem map (floats): x0@0 x1@3600 x2@7200 x3@10800 | xx@14400 idx@14528(..15528)
// gbuf@15528 pbuf@16040 sts@16168 | scr@16552..26952   (no overlaps)
// ---------------------------------------------------------------------------
extern "C" __global__ void __launch_bounds__(NTHR, 2)
dgcnn_fused(Ptrs P, float* __restrict__ out)
{
    extern __shared__ float sm[];
    float* x0   = sm;
    float* x1   = sm + 3600;
    float* x2   = sm + 7200;
    float* x3   = sm + 10800;
    float* xx   = sm + 14400;
    int*   idx  = (int*)(sm + 14528);
    float* gbuf = sm + 15528;
    float* pbuf = sm + 16040;
    float* sts  = sm + 16168;
    float* scr  = sm + 16552;

    const int tid = threadIdx.x;
    const int b = blockIdx.x;

    for (int i = tid; i < 32 * 12; i += NTHR) {
        int g = i >> 5, c = i & 31, si = g >> 1;
        sts[i] = (g & 1) ? P.t[si][c] : P.s[si][c];
    }

    // ---- stage 0: x0 = lrelu(s0*(W0 @ obs_rows)+t0) ----
    for (int i = tid; i < 3000; i += NTHR) scr[i] = P.obs[b * 3000 + i];
    for (int i = tid; i < 960; i += NTHR)  scr[3072 + i] = P.W0[i];
    __syncthreads();
    for (int tt = tid; tt < 32 * NPT; tt += NTHR) {
        const int o = tt & 31, n = tt >> 5;
        const u64* wr = (const u64*)(scr + 3072 + o * 30);
        const u64* xr = (const u64*)(scr + n * 30);
        u64 s0 = 0, s1 = 0;
        #pragma unroll
        for (int i = 0; i < 14; i += 2) { fma2(s0, wr[i], xr[i]); fma2(s1, wr[i+1], xr[i+1]); }
        fma2(s0, wr[14], xr[14]);
        x0[n * XS + o] = lrelu(fmaf(sts[o], hsum(add2(s0, s1)), sts[32 + o]));
    }
    __syncthreads();

    // ---- 3x (kNN + EdgeConv) ----
    knn_stage(x0, xx, idx, scr, tid);
    edge_dual(x0, x1, idx, P.W1, P.W2, sts + 64, sts + 96, sts + 128, sts + 160,
              scr, x2, x3, tid);
    knn_stage(x1, xx, idx, scr, tid);
    edge_dual(x1, x2, idx, P.W3, P.W4, sts + 192, sts + 224, sts + 256, sts + 288,
              scr, x0, x3, tid);
    knn_stage(x2, xx, idx, scr, tid);
    edge_single(x2, x3, idx, P.W5, sts + 320, sts + 352, scr, tid);

    // ---- W6 (512x96) + global max -> g[512]; 2 outputs per thread, 4 accums ----
    #pragma unroll 1
    for (int rep = 0; rep < 2; ++rep) {
        const int o = tid + rep * NTHR;
        u64 w[48];
        const ulonglong2* wr = (const ulonglong2*)(P.W6 + o * 96);
        #pragma unroll
        for (int q = 0; q < 24; ++q) { ulonglong2 v = __ldg(wr + q); w[2*q] = v.x; w[2*q+1] = v.y; }
        float gmax = -3.4e38f;
        for (int n = 0; n < NPT; ++n) {
            u64 s0 = 0, s1 = 0, s2 = 0, s3 = 0;
            const ulonglong2* a  = (const ulonglong2*)(x1 + n * XS);
            const ulonglong2* bb = (const ulonglong2*)(x2 + n * XS);
            const ulonglong2* cc = (const ulonglong2*)(x3 + n * XS);
            #pragma unroll
            for (int i = 0; i < 8; ++i) { ulonglong2 v = a[i];  fma2(s0, w[2*i],    v.x); fma2(s1, w[2*i+1],    v.y); }
            #pragma unroll
            for (int i = 0; i < 8; ++i) { ulonglong2 v = bb[i]; fma2(s2, w[16+2*i], v.x); fma2(s3, w[16+2*i+1], v.y); }
            #pragma unroll
            for (int i = 0; i < 8; ++i) { ulonglong2 v = cc[i]; fma2(s0, w[32+2*i], v.x); fma2(s1, w[32+2*i+1], v.y); }
            gmax = fmaxf(gmax, hsum(add2(add2(s0, s2), add2(s1, s3))));
        }
        gbuf[o] = lrelu(fmaf(__ldg(P.s[6] + o), gmax, __ldg(P.t[6] + o)));
    }
    __syncthreads();

    // ---- p[o] = W7[o,:512] . g ----
    if (tid < 128) {
        const ulonglong2* wr = (const ulonglong2*)(P.W7 + tid * 608);
        const ulonglong2* gv = (const ulonglong2*)gbuf;
        u64 s0 = 0, s1 = 0, s2 = 0, s3 = 0;
        #pragma unroll 16
        for (int q = 0; q < 128; q += 2) {
            ulonglong2 w0 = __ldg(wr + q); ulonglong2 g0 = gv[q];
            ulonglong2 w1 = __ldg(wr + q + 1); ulonglong2 g1 = gv[q + 1];
            fma2(s0, w0.x, g0.x); fma2(s1, w0.y, g0.y);
            fma2(s2, w1.x, g1.x); fma2(s3, w1.y, g1.y);
        }
        pbuf[tid] = hsum(add2(add2(s0, s2), add2(s1, s3)));
    }
    __syncthreads();

    // ---- h2[n][o] = lrelu(s7*(p[o] + W7[o,512:608].xc[n]) + t7) ----
    // h2 rows 0..77 in scr, rows 78..99 in x0 (both stride 132)
    {
        const int o = tid & 127, nh = tid >> 7;
        u64 w[48];
        const ulonglong2* wr = (const ulonglong2*)(P.W7 + o * 608 + 512);
        #pragma unroll
        for (int q = 0; q < 24; ++q) { ulonglong2 v = __ldg(wr + q); w[2*q] = v.x; w[2*q+1] = v.y; }
        const float po = pbuf[o];
        const float so = __ldg(P.s[7] + o), to = __ldg(P.t[7] + o);
        for (int n = nh * 50; n < nh * 50 + 50; ++n) {
            u64 s0 = 0, s1 = 0, s2 = 0, s3 = 0;
            const ulonglong2* a  = (const ulonglong2*)(x1 + n * XS);
            const ulonglong2* bb = (const ulonglong2*)(x2 + n * XS);
            const ulonglong2* cc = (const ulonglong2*)(x3 + n * XS);
            #pragma unroll
            for (int i = 0; i < 8; ++i) { ulonglong2 v = a[i];  fma2(s0, w[2*i],    v.x); fma2(s1, w[2*i+1],    v.y); }
            #pragma unroll
            for (int i = 0; i < 8; ++i) { ulonglong2 v = bb[i]; fma2(s2, w[16+2*i], v.x); fma2(s3, w[16+2*i+1], v.y); }
            #pragma unroll
            for (int i = 0; i < 8; ++i) { ulonglong2 v = cc[i]; fma2(s0, w[32+2*i], v.x); fma2(s1, w[32+2*i+1], v.y); }
            float* hr = (n < 78 ? scr + n * 132 : x0 + (n - 78) * 132);
            hr[o] = lrelu(fmaf(so, po + hsum(add2(add2(s0, s2), add2(s1, s3))), to));
        }
    }
    __syncthreads();

    // ---- stage W8 (padded stride 132) into x1/x2 region (dead now) ----
    {
        float* w8p = x1;
        for (int i = tid; i < 4096; i += NTHR) {
            int o2 = i >> 7, c = i & 127;
            w8p[o2 * 132 + c] = P.W8[i];
        }
    }
    __syncthreads();

    // ---- W8 (32x128): y8 -> x3 region ----
    {
        const float* w8p = x1;
        float* y8 = x3;
        const float s8v = __ldg(P.s[8] + (tid & 31));
        const float t8v = __ldg(P.t[8] + (tid & 31));
        for (int tt = tid; tt < 32 * NPT; tt += NTHR) {
            const int o2 = tt & 31, n = tt >> 5;
            const float* hr = (n < 78 ? scr + n * 132 : x0 + (n - 78) * 132);
            const ulonglong2* wr = (const ulonglong2*)(w8p + o2 * 132);
            const ulonglong2* hv = (const ulonglong2*)hr;
            u64 s0 = 0, s1 = 0;
            #pragma unroll
            for (int q = 0; q < 32; ++q) {
                ulonglong2 wv = wr[q]; ulonglong2 h = hv[q];
                fma2(s0, wv.x, h.x); fma2(s1, wv.y, h.y);
            }
            y8[n * XS + o2] = lrelu(fmaf(s8v, hsum(add2(s0, s1)), t8v));
        }
    }
    __syncthreads();

    // ---- final head ----
    if (tid < NPT) {
        u64 w[16];
        const ulonglong2* wr = (const ulonglong2*)P.W9;
        #pragma unroll
        for (int q = 0; q < 8; ++q) { ulonglong2 v = __ldg(wr + q); w[2*q] = v.x; w[2*q+1] = v.y; }
        out[b * NPT + tid] = dot32s(w, x3 + tid * XS);
    }
}

extern "C" void kernel_launch(void* const* d_in, const int* in_sizes, int n_in,
                              void* d_out, int out_size)
{
    Ptrs P;
    P.obs = (const float*)d_in[0];
    P.W0 = (const float*)d_in[1];  P.W1 = (const float*)d_in[2];
    P.W2 = (const float*)d_in[3];  P.W3 = (const float*)d_in[4];
    P.W4 = (const float*)d_in[5];  P.W5 = (const float*)d_in[6];
    P.W6 = (const float*)d_in[7];  P.W7 = (const float*)d_in[8];
    P.W8 = (const float*)d_in[9];  P.W9 = (const float*)d_in[10];

    const bool separated = (n_in > 17 && in_sizes[17] == 512);
    for (int i = 0; i < 9; ++i) {
        if (separated) {
            P.s[i] = (const float*)d_in[11 + i];
            P.t[i] = (const float*)d_in[20 + i];
        } else {
            P.s[i] = (const float*)d_in[11 + 2 * i];
            P.t[i] = (const float*)d_in[12 + 2 * i];
        }
    }

    const int B = in_sizes[0] / 3000;
    const int smem_bytes = 26952 * 4;   // 105.3 KB -> 2 CTAs/SM
    cudaFuncSetAttribute(dgcnn_fused, cudaFuncAttributeMaxDynamicSharedMemorySize, smem_bytes);
    dgcnn_fused<<<B, NTHR, smem_bytes>>>(P, (float*)d_out);
}

// round 6
// speedup vs baseline: 2.4771x; 2.4771x over previous
#include <cuda_runtime.h>

#define NPT   100
#define KNN   10
#define XS    36
#define NTHR  256

typedef unsigned long long u64;

struct Ptrs {
    const float* obs;
    const float* W0; const float* W1; const float* W2; const float* W3; const float* W4;
    const float* W5; const float* W6; const float* W7; const float* W8; const float* W9;
    const float* s[9]; const float* t[9];
};

__device__ __forceinline__ float lrelu(float v) { return fmaxf(v, 0.2f * v); }

__device__ __forceinline__ u64 pack2(float lo, float hi) {
    u64 r; asm("mov.b64 %0,{%1,%2};" : "=l"(r) : "f"(lo), "f"(hi)); return r;
}
__device__ __forceinline__ void fma2(u64& d, u64 a, u64 b) {
    asm("fma.rn.f32x2 %0,%1,%2,%0;" : "+l"(d) : "l"(a), "l"(b));
}
__device__ __forceinline__ u64 add2(u64 a, u64 b) {
    u64 r; asm("add.rn.f32x2 %0,%1,%2;" : "=l"(r) : "l"(a), "l"(b)); return r;
}
__device__ __forceinline__ void unpack2(u64 v, float& a, float& b) {
    asm("mov.b64 {%0,%1},%2;" : "=f"(a), "=f"(b) : "l"(v));
}
__device__ __forceinline__ float hsum(u64 v) { float a, b; unpack2(v, a, b); return a + b; }

__device__ __forceinline__ void ldrow(u64* r, const float* p) {
    const ulonglong2* q = (const ulonglong2*)p;
    #pragma unroll
    for (int i = 0; i < 8; ++i) { ulonglong2 v = q[i]; r[2*i] = v.x; r[2*i+1] = v.y; }
}
__device__ __forceinline__ float dot32s(const u64* a, const float* b) {
    const ulonglong2* q = (const ulonglong2*)b;
    u64 s0 = 0, s1 = 0;
    #pragma unroll
    for (int i = 0; i < 8; ++i) { ulonglong2 v = q[i]; fma2(s0, a[2*i], v.x); fma2(s1, a[2*i+1], v.y); }
    return hsum(add2(s0, s1));
}
__device__ __forceinline__ float dot32ss(const float* a, const float* b) {
    const ulonglong2* pa = (const ulonglong2*)a;
    const ulonglong2* pb = (const ulonglong2*)b;
    u64 s0 = 0, s1 = 0;
    #pragma unroll
    for (int i = 0; i < 8; ++i) {
        ulonglong2 va = pa[i], vb = pb[i];
        fma2(s0, va.x, vb.x); fma2(s1, va.y, vb.y);
    }
    return hsum(add2(s0, s1));
}

// ---------------------------------------------------------------------------
// kNN: 200 threads scan j-halves of 50 -> per-half top-10; 100 threads merge.
// ---------------------------------------------------------------------------
__device__ void knn_stage(const float* __restrict__ xsrc, float* __restrict__ xx,
                          int* __restrict__ idx, float* __restrict__ scr, int tid)
{
    if (tid < NPT) {
        xx[tid] = dot32ss(xsrc + tid * XS, xsrc + tid * XS);
    }
    __syncthreads();
    float* vbuf = scr;                    // 200*10
    int*   ibuf = (int*)(scr + 2048);     // 200*10
    if (tid < 2 * NPT) {
        const int n = tid % NPT, h = tid / NPT;
        u64 xi[16]; ldrow(xi, xsrc + n * XS);
        const float nxi = xx[n];
        float v[KNN]; int id[KNN];
        #pragma unroll
        for (int p = 0; p < KNN; ++p) { v[p] = -3.4e38f; id[p] = 0; }
        for (int j = h * 50; j < h * 50 + 50; ++j) {
            float d = 2.f * dot32s(xi, xsrc + j * XS) - nxi - xx[j];
            if (d > v[KNN - 1]) {
                float dv = d; int di = j;
                #pragma unroll
                for (int p = 0; p < KNN; ++p) {
                    if (dv > v[p]) {
                        float tv = v[p]; int ti = id[p];
                        v[p] = dv; id[p] = di; dv = tv; di = ti;
                    }
                }
            }
        }
        #pragma unroll
        for (int p = 0; p < KNN; ++p) { vbuf[tid * KNN + p] = v[p]; ibuf[tid * KNN + p] = id[p]; }
    }
    __syncthreads();
    if (tid < NPT) {
        const float* va = vbuf + tid * KNN; const float* vb = vbuf + (tid + NPT) * KNN;
        const int*   ia = ibuf + tid * KNN; const int*   ib = ibuf + (tid + NPT) * KNN;
        int pa = 0, pb = 0;
        #pragma unroll
        for (int p = 0; p < KNN; ++p) {
            bool ta = va[pa] >= vb[pb];
            idx[tid * KNN + p] = ta ? ia[pa] : ib[pb];
            if (ta) ++pa; else ++pb;
        }
    }
    __syncthreads();
}

// ---------------------------------------------------------------------------
// Dual-conv EdgeConv with U/V factoring (registers: only m[16]+z[16]):
//   U'[j][o] = sa[o]*(Wa[o].x_j)          (stride 34, 8B-aligned rows)
//   V'[n][o] = sa[o]*(Wd[o].x_n) + ta[o]  (stride 34)
//   y1(n,j)[o] = lrelu(U'[j][o] + V'[n][o]); z = Wbt.y1; out = lrelu(sb*max+tb)
// ---------------------------------------------------------------------------
__device__ void edge_dual(const float* __restrict__ xsrc, float* __restrict__ dest,
                          const int* __restrict__ idx,
                          const float* __restrict__ Wg, const float* __restrict__ Wbg,
                          const float* __restrict__ sa, const float* __restrict__ ta,
                          const float* __restrict__ sb, const float* __restrict__ tb,
                          float* __restrict__ scr,
                          float* __restrict__ pmA, float* __restrict__ pmB, int tid)
{
    float* Wa  = scr;             // 1024
    float* Wd  = scr + 1024;      // 1024
    float* Wbt = scr + 2048;      // 1024
    float* U   = scr + 3072;      // 100*34 = 3400
    float* V   = scr + 6472;      // 100*34 = 3400
    for (int i = tid; i < 1024; i += NTHR) {
        int o = i >> 5, c = i & 31;
        float wa = Wg[o * 64 + c];
        Wa[i] = wa;
        Wd[i] = Wg[o * 64 + 32 + c] - wa;
        Wbt[c * 32 + o] = Wbg[i];
    }
    __syncthreads();

    // phase 1: per-point U'/V'
    if (tid < 2 * NPT) {
        const int n = tid % NPT;
        u64 xr[16]; ldrow(xr, xsrc + n * XS);
        if (tid < NPT) {
            #pragma unroll 4
            for (int o = 0; o < 32; ++o)
                U[n * 34 + o] = sa[o] * dot32s(xr, Wa + o * 32);
        } else {
            #pragma unroll 4
            for (int o = 0; o < 32; ++o)
                V[n * 34 + o] = fmaf(sa[o], dot32s(xr, Wd + o * 32), ta[o]);
        }
    }
    __syncthreads();

    // phase 2: per-edge lrelu + second conv + max over 5 nbrs per half
    if (tid < 2 * NPT) {
        const int n = tid % NPT, kh = tid / NPT;
        const u64* vq = (const u64*)(V + n * 34);
        u64 m[16];
        #pragma unroll
        for (int i = 0; i < 16; ++i) m[i] = pack2(-3.4e38f, -3.4e38f);
        for (int kk = 0; kk < 5; ++kk) {
            const int j = idx[n * KNN + kh * 5 + kk];
            const u64* uq = (const u64*)(U + j * 34);
            u64 z[16];
            #pragma unroll
            for (int i = 0; i < 16; ++i) z[i] = 0;
            #pragma unroll 4
            for (int p = 0; p < 16; ++p) {
                float ya, yb; unpack2(add2(uq[p], vq[p]), ya, yb);
                const u64 y2a = pack2(lrelu(ya), lrelu(ya));
                const u64 y2b = pack2(lrelu(yb), lrelu(yb));
                const ulonglong2* wbA = (const ulonglong2*)(Wbt + (2 * p) * 32);
                const ulonglong2* wbB = (const ulonglong2*)(Wbt + (2 * p + 1) * 32);
                #pragma unroll
                for (int i = 0; i < 8; ++i) {
                    ulonglong2 wA = wbA[i], wB = wbB[i];
                    fma2(z[2*i],     y2a, wA.x); fma2(z[2*i + 1], y2a, wA.y);
                    fma2(z[2*i],     y2b, wB.x); fma2(z[2*i + 1], y2b, wB.y);
                }
            }
            #pragma unroll
            for (int i = 0; i < 16; ++i) {
                float za, zb, ma, mb;
                unpack2(z[i], za, zb); unpack2(m[i], ma, mb);
                m[i] = pack2(fmaxf(ma, za), fmaxf(mb, zb));
            }
        }
        float* pr = (kh == 0 ? pmA : pmB) + n * XS;
        #pragma unroll
        for (int i = 0; i < 16; ++i) {
            float a, b; unpack2(m[i], a, b);
            pr[2*i] = a; pr[2*i+1] = b;
        }
    }
    __syncthreads();
    for (int i = tid; i < 32 * NPT; i += NTHR) {
        const int n = i >> 5, o = i & 31;
        float mv = fmaxf(pmA[n * XS + o], pmB[n * XS + o]);
        dest[n * XS + o] = lrelu(fmaf(sb[o], mv, tb[o]));
    }
    __syncthreads();
}

// ---------------------------------------------------------------------------
// Single-conv EdgeConv with U/V factoring: out[n][o] =
//   lrelu(sb*(max_k U[idx[n][k]][o] + V[n][o]) + tb). No per-edge GEMM.
// ---------------------------------------------------------------------------
__device__ void edge_single(const float* __restrict__ xsrc, float* __restrict__ dest,
                            const int* __restrict__ idx,
                            const float* __restrict__ Wg,
                            const float* __restrict__ sb, const float* __restrict__ tb,
                            float* __restrict__ scr, int tid)
{
    float* Wa = scr;             // 1024
    float* Wd = scr + 1024;      // 1024
    float* U  = scr + 3072;      // 100*33
    float* V  = scr + 6472;      // 100*33
    for (int i = tid; i < 1024; i += NTHR) {
        int o = i >> 5, c = i & 31;
        float wa = Wg[o * 64 + c];
        Wa[i] = wa;
        Wd[i] = Wg[o * 64 + 32 + c] - wa;
    }
    __syncthreads();
    if (tid < 2 * NPT) {
        const int n = tid % NPT;
        u64 xr[16]; ldrow(xr, xsrc + n * XS);
        if (tid < NPT) {
            #pragma unroll 4
            for (int o = 0; o < 32; ++o)
                U[n * 33 + o] = dot32s(xr, Wa + o * 32);
        } else {
            #pragma unroll 4
            for (int o = 0; o < 32; ++o)
                V[n * 33 + o] = dot32s(xr, Wd + o * 32);
        }
    }
    __syncthreads();
    if (tid < NPT) {
        const int n = tid;
        float m[32];
        #pragma unroll
        for (int o = 0; o < 32; ++o) m[o] = -3.4e38f;
        #pragma unroll 1
        for (int kk = 0; kk < KNN; ++kk) {
            const int j = idx[n * KNN + kk];
            const float* urow = U + j * 33;
            #pragma unroll
            for (int o = 0; o < 32; ++o) m[o] = fmaxf(m[o], urow[o]);
        }
        #pragma unroll
        for (int o = 0; o < 32; ++o)
            dest[n * XS + o] = lrelu(fmaf(sb[o], m[o] + V[n * 33 + o], tb[o]));
    }
    __syncthreads();
}

// ---------------------------------------------------------------------------
// Main fused kernel: one CTA per batch element, 256 threads, 2 CTAs/SM.
// smem map (floats): x0@0 x1@3600 x2@7200 x3@10800 | xx@14400 idx@14528(..15528)
// gbuf@15528 pbuf@16040 sts@16168 | scr@16552..26952   (no overlaps)
// ---------------------------------------------------------------------------
extern "C" __global__ void __launch_bounds__(NTHR, 2)
dgcnn_fused(Ptrs P, float* __restrict__ out)
{
    extern __shared__ float sm[];
    float* x0   = sm;
    float* x1   = sm + 3600;
    float* x2   = sm + 7200;
    float* x3   = sm + 10800;
    float* xx   = sm + 14400;
    int*   idx  = (int*)(sm + 14528);
    float* gbuf = sm + 15528;
    float* pbuf = sm + 16040;
    float* sts  = sm + 16168;
    float* scr  = sm + 16552;

    const int tid = threadIdx.x;
    const int b = blockIdx.x;

    for (int i = tid; i < 32 * 12; i += NTHR) {
        int g = i >> 5, c = i & 31, si = g >> 1;
        sts[i] = (g & 1) ? P.t[si][c] : P.s[si][c];
    }

    // ---- stage 0: x0 = lrelu(s0*(W0 @ obs_rows)+t0) ----
    for (int i = tid; i < 3000; i += NTHR) scr[i] = P.obs[b * 3000 + i];
    for (int i = tid; i < 960; i += NTHR)  scr[3072 + i] = P.W0[i];
    __syncthreads();
    for (int tt = tid; tt < 32 * NPT; tt += NTHR) {
        const int o = tt & 31, n = tt >> 5;
        const u64* wr = (const u64*)(scr + 3072 + o * 30);
        const u64* xr = (const u64*)(scr + n * 30);
        u64 s0 = 0, s1 = 0;
        #pragma unroll
        for (int i = 0; i < 14; i += 2) { fma2(s0, wr[i], xr[i]); fma2(s1, wr[i+1], xr[i+1]); }
        fma2(s0, wr[14], xr[14]);
        x0[n * XS + o] = lrelu(fmaf(sts[o], hsum(add2(s0, s1)), sts[32 + o]));
    }
    __syncthreads();

    // ---- 3x (kNN + EdgeConv) ----
    knn_stage(x0, xx, idx, scr, tid);
    edge_dual(x0, x1, idx, P.W1, P.W2, sts + 64, sts + 96, sts + 128, sts + 160,
              scr, x2, x3, tid);
    knn_stage(x1, xx, idx, scr, tid);
    edge_dual(x1, x2, idx, P.W3, P.W4, sts + 192, sts + 224, sts + 256, sts + 288,
              scr, x0, x3, tid);
    knn_stage(x2, xx, idx, scr, tid);
    edge_single(x2, x3, idx, P.W5, sts + 320, sts + 352, scr, tid);

    // ---- W6 (512x96) + global max -> g[512]; 2 outputs per thread, 4 accums ----
    #pragma unroll 1
    for (int rep = 0; rep < 2; ++rep) {
        const int o = tid + rep * NTHR;
        u64 w[48];
        const ulonglong2* wr = (const ulonglong2*)(P.W6 + o * 96);
        #pragma unroll
        for (int q = 0; q < 24; ++q) { ulonglong2 v = __ldg(wr + q); w[2*q] = v.x; w[2*q+1] = v.y; }
        float gmax = -3.4e38f;
        for (int n = 0; n < NPT; ++n) {
            u64 s0 = 0, s1 = 0, s2 = 0, s3 = 0;
            const ulonglong2* a  = (const ulonglong2*)(x1 + n * XS);
            const ulonglong2* bb = (const ulonglong2*)(x2 + n * XS);
            const ulonglong2* cc = (const ulonglong2*)(x3 + n * XS);
            #pragma unroll
            for (int i = 0; i < 8; ++i) { ulonglong2 v = a[i];  fma2(s0, w[2*i],    v.x); fma2(s1, w[2*i+1],    v.y); }
            #pragma unroll
            for (int i = 0; i < 8; ++i) { ulonglong2 v = bb[i]; fma2(s2, w[16+2*i], v.x); fma2(s3, w[16+2*i+1], v.y); }
            #pragma unroll
            for (int i = 0; i < 8; ++i) { ulonglong2 v = cc[i]; fma2(s0, w[32+2*i], v.x); fma2(s1, w[32+2*i+1], v.y); }
            gmax = fmaxf(gmax, hsum(add2(add2(s0, s2), add2(s1, s3))));
        }
        gbuf[o] = lrelu(fmaf(__ldg(P.s[6] + o), gmax, __ldg(P.t[6] + o)));
    }
    __syncthreads();

    // ---- p[o] = W7[o,:512] . g ----
    if (tid < 128) {
        const ulonglong2* wr = (const ulonglong2*)(P.W7 + tid * 608);
        const ulonglong2* gv = (const ulonglong2*)gbuf;
        u64 s0 = 0, s1 = 0, s2 = 0, s3 = 0;
        #pragma unroll 16
        for (int q = 0; q < 128; q += 2) {
            ulonglong2 w0 = __ldg(wr + q); ulonglong2 g0 = gv[q];
            ulonglong2 w1 = __ldg(wr + q + 1); ulonglong2 g1 = gv[q + 1];
            fma2(s0, w0.x, g0.x); fma2(s1, w0.y, g0.y);
            fma2(s2, w1.x, g1.x); fma2(s3, w1.y, g1.y);
        }
        pbuf[tid] = hsum(add2(add2(s0, s2), add2(s1, s3)));
    }
    __syncthreads();

    // ---- h2[n][o] = lrelu(s7*(p[o] + W7[o,512:608].xc[n]) + t7) ----
    // h2 rows 0..77 in scr, rows 78..99 in x0 (both stride 132)
    {
        const int o = tid & 127, nh = tid >> 7;
        u64 w[48];
        const ulonglong2* wr = (const ulonglong2*)(P.W7 + o * 608 + 512);
        #pragma unroll
        for (int q = 0; q < 24; ++q) { ulonglong2 v = __ldg(wr + q); w[2*q] = v.x; w[2*q+1] = v.y; }
        const float po = pbuf[o];
        const float so = __ldg(P.s[7] + o), to = __ldg(P.t[7] + o);
        for (int n = nh * 50; n < nh * 50 + 50; ++n) {
            u64 s0 = 0, s1 = 0, s2 = 0, s3 = 0;
            const ulonglong2* a  = (const ulonglong2*)(x1 + n * XS);
            const ulonglong2* bb = (const ulonglong2*)(x2 + n * XS);
            const ulonglong2* cc = (const ulonglong2*)(x3 + n * XS);
            #pragma unroll
            for (int i = 0; i < 8; ++i) { ulonglong2 v = a[i];  fma2(s0, w[2*i],    v.x); fma2(s1, w[2*i+1],    v.y); }
            #pragma unroll
            for (int i = 0; i < 8; ++i) { ulonglong2 v = bb[i]; fma2(s2, w[16+2*i], v.x); fma2(s3, w[16+2*i+1], v.y); }
            #pragma unroll
            for (int i = 0; i < 8; ++i) { ulonglong2 v = cc[i]; fma2(s0, w[32+2*i], v.x); fma2(s1, w[32+2*i+1], v.y); }
            float* hr = (n < 78 ? scr + n * 132 : x0 + (n - 78) * 132);
            hr[o] = lrelu(fmaf(so, po + hsum(add2(add2(s0, s2), add2(s1, s3))), to));
        }
    }
    __syncthreads();

    // ---- stage W8 (padded stride 132) into x1/x2 region (dead now) ----
    {
        float* w8p = x1;
        for (int i = tid; i < 4096; i += NTHR) {
            int o2 = i >> 7, c = i & 127;
            w8p[o2 * 132 + c] = P.W8[i];
        }
    }
    __syncthreads();

    // ---- W8 (32x128): y8 -> x3 region ----
    {
        const float* w8p = x1;
        float* y8 = x3;
        const float s8v = __ldg(P.s[8] + (tid & 31));
        const float t8v = __ldg(P.t[8] + (tid & 31));
        for (int tt = tid; tt < 32 * NPT; tt += NTHR) {
            const int o2 = tt & 31, n = tt >> 5;
            const float* hr = (n < 78 ? scr + n * 132 : x0 + (n - 78) * 132);
            const ulonglong2* wr = (const ulonglong2*)(w8p + o2 * 132);
            const ulonglong2* hv = (const ulonglong2*)hr;
            u64 s0 = 0, s1 = 0;
            #pragma unroll
            for (int q = 0; q < 32; ++q) {
                ulonglong2 wv = wr[q]; ulonglong2 h = hv[q];
                fma2(s0, wv.x, h.x); fma2(s1, wv.y, h.y);
            }
            y8[n * XS + o2] = lrelu(fmaf(s8v, hsum(add2(s0, s1)), t8v));
        }
    }
    __syncthreads();

    // ---- final head ----
    if (tid < NPT) {
        u64 w[16];
        const ulonglong2* wr = (const ulonglong2*)P.W9;
        #pragma unroll
        for (int q = 0; q < 8; ++q) { ulonglong2 v = __ldg(wr + q); w[2*q] = v.x; w[2*q+1] = v.y; }
        out[b * NPT + tid] = dot32s(w, x3 + tid * XS);
    }
}

extern "C" void kernel_launch(void* const* d_in, const int* in_sizes, int n_in,
                              void* d_out, int out_size)
{
    Ptrs P;
    P.obs = (const float*)d_in[0];
    P.W0 = (const float*)d_in[1];  P.W1 = (const float*)d_in[2];
    P.W2 = (const float*)d_in[3];  P.W3 = (const float*)d_in[4];
    P.W4 = (const float*)d_in[5];  P.W5 = (const float*)d_in[6];
    P.W6 = (const float*)d_in[7];  P.W7 = (const float*)d_in[8];
    P.W8 = (const float*)d_in[9];  P.W9 = (const float*)d_in[10];

    const bool separated = (n_in > 17 && in_sizes[17] == 512);
    for (int i = 0; i < 9; ++i) {
        if (separated) {
            P.s[i] = (const float*)d_in[11 + i];
            P.t[i] = (const float*)d_in[20 + i];
        } else {
            P.s[i] = (const float*)d_in[11 + 2 * i];
            P.t[i] = (const float*)d_in[12 + 2 * i];
        }
    }

    const int B = in_sizes[0] / 3000;
    const int smem_bytes = 26952 * 4;   // 105.3 KB -> 2 CTAs/SM
    cudaFuncSetAttribute(dgcnn_fused, cudaFuncAttributeMaxDynamicSharedMemorySize, smem_bytes);
    dgcnn_fused<<<B, NTHR, smem_bytes>>>(P, (float*)d_out);
}

// round 7
// speedup vs baseline: 2.5592x; 1.0331x over previous
#include <cuda_runtime.h>

#define NPT   100
#define KNN   10
#define XS    36
#define NTHR  256

typedef unsigned long long u64;

struct Ptrs {
    const float* obs;
    const float* W0; const float* W1; const float* W2; const float* W3; const float* W4;
    const float* W5; const float* W6; const float* W7; const float* W8; const float* W9;
    const float* s[9]; const float* t[9];
};

__device__ __forceinline__ float lrelu(float v) { return fmaxf(v, 0.2f * v); }

__device__ __forceinline__ u64 pack2(float lo, float hi) {
    u64 r; asm("mov.b64 %0,{%1,%2};" : "=l"(r) : "f"(lo), "f"(hi)); return r;
}
__device__ __forceinline__ void fma2(u64& d, u64 a, u64 b) {
    asm("fma.rn.f32x2 %0,%1,%2,%0;" : "+l"(d) : "l"(a), "l"(b));
}
__device__ __forceinline__ u64 add2(u64 a, u64 b) {
    u64 r; asm("add.rn.f32x2 %0,%1,%2;" : "=l"(r) : "l"(a), "l"(b)); return r;
}
__device__ __forceinline__ void unpack2(u64 v, float& a, float& b) {
    asm("mov.b64 {%0,%1},%2;" : "=f"(a), "=f"(b) : "l"(v));
}
__device__ __forceinline__ float hsum(u64 v) { float a, b; unpack2(v, a, b); return a + b; }
__device__ __forceinline__ u64 max2(u64 x, u64 y) {
    float xa, xb, ya, yb; unpack2(x, xa, xb); unpack2(y, ya, yb);
    return pack2(fmaxf(xa, ya), fmaxf(xb, yb));
}

__device__ __forceinline__ void ldrow(u64* r, const float* p) {
    const ulonglong2* q = (const ulonglong2*)p;
    #pragma unroll
    for (int i = 0; i < 8; ++i) { ulonglong2 v = q[i]; r[2*i] = v.x; r[2*i+1] = v.y; }
}
__device__ __forceinline__ float dot32s(const u64* a, const float* b) {
    const ulonglong2* q = (const ulonglong2*)b;
    u64 s0 = 0, s1 = 0;
    #pragma unroll
    for (int i = 0; i < 8; ++i) { ulonglong2 v = q[i]; fma2(s0, a[2*i], v.x); fma2(s1, a[2*i+1], v.y); }
    return hsum(add2(s0, s1));
}
__device__ __forceinline__ float dot32ss(const float* a, const float* b) {
    const ulonglong2* pa = (const ulonglong2*)a;
    const ulonglong2* pb = (const ulonglong2*)b;
    u64 s0 = 0, s1 = 0;
    #pragma unroll
    for (int i = 0; i < 8; ++i) {
        ulonglong2 va = pa[i], vb = pb[i];
        fma2(s0, va.x, vb.x); fma2(s1, va.y, vb.y);
    }
    return hsum(add2(s0, s1));
}

// ---------------------------------------------------------------------------
// kNN: 200 threads scan j-halves of 50 -> per-half top-10; 100 threads merge.
// ---------------------------------------------------------------------------
__device__ void knn_stage(const float* __restrict__ xsrc, float* __restrict__ xx,
                          int* __restrict__ idx, float* __restrict__ scr, int tid)
{
    if (tid < NPT) {
        xx[tid] = dot32ss(xsrc + tid * XS, xsrc + tid * XS);
    }
    __syncthreads();
    float* vbuf = scr;                    // 200*10
    int*   ibuf = (int*)(scr + 2048);     // 200*10
    if (tid < 2 * NPT) {
        const int n = tid % NPT, h = tid / NPT;
        u64 xi[16]; ldrow(xi, xsrc + n * XS);
        const float nxi = xx[n];
        float v[KNN]; int id[KNN];
        #pragma unroll
        for (int p = 0; p < KNN; ++p) { v[p] = -3.4e38f; id[p] = 0; }
        for (int j = h * 50; j < h * 50 + 50; ++j) {
            float d = 2.f * dot32s(xi, xsrc + j * XS) - nxi - xx[j];
            if (d > v[KNN - 1]) {
                float dv = d; int di = j;
                #pragma unroll
                for (int p = 0; p < KNN; ++p) {
                    if (dv > v[p]) {
                        float tv = v[p]; int ti = id[p];
                        v[p] = dv; id[p] = di; dv = tv; di = ti;
                    }
                }
            }
        }
        #pragma unroll
        for (int p = 0; p < KNN; ++p) { vbuf[tid * KNN + p] = v[p]; ibuf[tid * KNN + p] = id[p]; }
    }
    __syncthreads();
    if (tid < NPT) {
        const float* va = vbuf + tid * KNN; const float* vb = vbuf + (tid + NPT) * KNN;
        const int*   ia = ibuf + tid * KNN; const int*   ib = ibuf + (tid + NPT) * KNN;
        int pa = 0, pb = 0;
        #pragma unroll
        for (int p = 0; p < KNN; ++p) {
            bool ta = va[pa] >= vb[pb];
            idx[tid * KNN + p] = ta ? ia[pa] : ib[pb];
            if (ta) ++pa; else ++pb;
        }
    }
    __syncthreads();
}

// ---------------------------------------------------------------------------
// Dual-conv EdgeConv with U/V factoring + neighbor-batched second conv.
//   U'[j][o] = sa[o]*(Wa[o].x_j), V'[n][o] = sa[o]*(Wd[o].x_n)+ta[o] (stride 34)
//   phase 2: per (n, kh-half of 5 nbrs): o2 halves of 16; neighbors in groups
//   3+2 sharing each Wbt row-half load across the group (z: 8 u64 per edge).
// ---------------------------------------------------------------------------
__device__ void edge_dual(const float* __restrict__ xsrc, float* __restrict__ dest,
                          const int* __restrict__ idx,
                          const float* __restrict__ Wg, const float* __restrict__ Wbg,
                          const float* __restrict__ sa, const float* __restrict__ ta,
                          const float* __restrict__ sb, const float* __restrict__ tb,
                          float* __restrict__ scr,
                          float* __restrict__ pmA, float* __restrict__ pmB, int tid)
{
    float* Wa  = scr;             // 1024
    float* Wd  = scr + 1024;      // 1024
    float* Wbt = scr + 2048;      // 1024
    float* U   = scr + 3072;      // 100*34 = 3400
    float* V   = scr + 6472;      // 100*34 = 3400
    for (int i = tid; i < 1024; i += NTHR) {
        int o = i >> 5, c = i & 31;
        float wa = Wg[o * 64 + c];
        Wa[i] = wa;
        Wd[i] = Wg[o * 64 + 32 + c] - wa;
        Wbt[c * 32 + o] = Wbg[i];
    }
    __syncthreads();

    // phase 1: per-point U'/V'
    if (tid < 2 * NPT) {
        const int n = tid % NPT;
        u64 xr[16]; ldrow(xr, xsrc + n * XS);
        if (tid < NPT) {
            #pragma unroll 4
            for (int o = 0; o < 32; ++o)
                U[n * 34 + o] = sa[o] * dot32s(xr, Wa + o * 32);
        } else {
            #pragma unroll 4
            for (int o = 0; o < 32; ++o)
                V[n * 34 + o] = fmaf(sa[o], dot32s(xr, Wd + o * 32), ta[o]);
        }
    }
    __syncthreads();

    // phase 2: neighbor-batched second conv + running max
    if (tid < 2 * NPT) {
        const int n = tid % NPT, kh = tid / NPT;
        const int base = n * KNN + kh * 5;
        const int j0 = idx[base], j1 = idx[base + 1], j2 = idx[base + 2];
        const int j3 = idx[base + 3], j4 = idx[base + 4];
        const u64* vq = (const u64*)(V + n * 34);
        const u64* ua = (const u64*)(U + j0 * 34);
        const u64* ub = (const u64*)(U + j1 * 34);
        const u64* uc = (const u64*)(U + j2 * 34);
        const u64* ud = (const u64*)(U + j3 * 34);
        const u64* ue = (const u64*)(U + j4 * 34);
        float* pr = (kh == 0 ? pmA : pmB) + n * XS;
        #pragma unroll 1
        for (int half = 0; half < 2; ++half) {
            const float* WbtH = Wbt + half * 16;
            u64 m[8];
            #pragma unroll
            for (int i = 0; i < 8; ++i) m[i] = pack2(-3.4e38f, -3.4e38f);
            // group of 3 neighbors (j0,j1,j2)
            {
                u64 za[8], zb[8], zc[8];
                #pragma unroll
                for (int i = 0; i < 8; ++i) { za[i] = 0; zb[i] = 0; zc[i] = 0; }
                #pragma unroll 4
                for (int p = 0; p < 16; ++p) {
                    const u64 vv = vq[p];
                    float a0, a1, b0, b1, c0, c1;
                    unpack2(add2(ua[p], vv), a0, a1);
                    unpack2(add2(ub[p], vv), b0, b1);
                    unpack2(add2(uc[p], vv), c0, c1);
                    a0 = lrelu(a0); a1 = lrelu(a1);
                    b0 = lrelu(b0); b1 = lrelu(b1);
                    c0 = lrelu(c0); c1 = lrelu(c1);
                    const u64 ya0 = pack2(a0, a0), ya1 = pack2(a1, a1);
                    const u64 yb0 = pack2(b0, b0), yb1 = pack2(b1, b1);
                    const u64 yc0 = pack2(c0, c0), yc1 = pack2(c1, c1);
                    const ulonglong2* wA = (const ulonglong2*)(WbtH + (2 * p) * 32);
                    const ulonglong2* wB = (const ulonglong2*)(WbtH + (2 * p + 1) * 32);
                    #pragma unroll
                    for (int q = 0; q < 4; ++q) {
                        ulonglong2 wa2 = wA[q], wb2 = wB[q];
                        fma2(za[2*q],   ya0, wa2.x); fma2(za[2*q+1], ya0, wa2.y);
                        fma2(za[2*q],   ya1, wb2.x); fma2(za[2*q+1], ya1, wb2.y);
                        fma2(zb[2*q],   yb0, wa2.x); fma2(zb[2*q+1], yb0, wa2.y);
                        fma2(zb[2*q],   yb1, wb2.x); fma2(zb[2*q+1], yb1, wb2.y);
                        fma2(zc[2*q],   yc0, wa2.x); fma2(zc[2*q+1], yc0, wa2.y);
                        fma2(zc[2*q],   yc1, wb2.x); fma2(zc[2*q+1], yc1, wb2.y);
                    }
                }
                #pragma unroll
                for (int i = 0; i < 8; ++i) m[i] = max2(m[i], max2(za[i], max2(zb[i], zc[i])));
            }
            // group of 2 neighbors (j3,j4)
            {
                u64 za[8], zb[8];
                #pragma unroll
                for (int i = 0; i < 8; ++i) { za[i] = 0; zb[i] = 0; }
                #pragma unroll 4
                for (int p = 0; p < 16; ++p) {
                    const u64 vv = vq[p];
                    float a0, a1, b0, b1;
                    unpack2(add2(ud[p], vv), a0, a1);
                    unpack2(add2(ue[p], vv), b0, b1);
                    a0 = lrelu(a0); a1 = lrelu(a1);
                    b0 = lrelu(b0); b1 = lrelu(b1);
                    const u64 ya0 = pack2(a0, a0), ya1 = pack2(a1, a1);
                    const u64 yb0 = pack2(b0, b0), yb1 = pack2(b1, b1);
                    const ulonglong2* wA = (const ulonglong2*)(WbtH + (2 * p) * 32);
                    const ulonglong2* wB = (const ulonglong2*)(WbtH + (2 * p + 1) * 32);
                    #pragma unroll
                    for (int q = 0; q < 4; ++q) {
                        ulonglong2 wa2 = wA[q], wb2 = wB[q];
                        fma2(za[2*q],   ya0, wa2.x); fma2(za[2*q+1], ya0, wa2.y);
                        fma2(za[2*q],   ya1, wb2.x); fma2(za[2*q+1], ya1, wb2.y);
                        fma2(zb[2*q],   yb0, wa2.x); fma2(zb[2*q+1], yb0, wa2.y);
                        fma2(zb[2*q],   yb1, wb2.x); fma2(zb[2*q+1], yb1, wb2.y);
                    }
                }
                #pragma unroll
                for (int i = 0; i < 8; ++i) m[i] = max2(m[i], max2(za[i], zb[i]));
            }
            u64* prq = (u64*)(pr + half * 16);
            #pragma unroll
            for (int i = 0; i < 8; ++i) prq[i] = m[i];
        }
    }
    __syncthreads();
    for (int i = tid; i < 32 * NPT; i += NTHR) {
        const int n = i >> 5, o = i & 31;
        float mv = fmaxf(pmA[n * XS + o], pmB[n * XS + o]);
        dest[n * XS + o] = lrelu(fmaf(sb[o], mv, tb[o]));
    }
    __syncthreads();
}

// ---------------------------------------------------------------------------
// Single-conv EdgeConv with U/V factoring: out[n][o] =
//   lrelu(sb*(max_k U[idx[n][k]][o] + V[n][o]) + tb). No per-edge GEMM.
// ---------------------------------------------------------------------------
__device__ void edge_single(const float* __restrict__ xsrc, float* __restrict__ dest,
                            const int* __restrict__ idx,
                            const float* __restrict__ Wg,
                            const float* __restrict__ sb, const float* __restrict__ tb,
                            float* __restrict__ scr, int tid)
{
    float* Wa = scr;             // 1024
    float* Wd = scr + 1024;      // 1024
    float* U  = scr + 3072;      // 100*33
    float* V  = scr + 6472;      // 100*33
    for (int i = tid; i < 1024; i += NTHR) {
        int o = i >> 5, c = i & 31;
        float wa = Wg[o * 64 + c];
        Wa[i] = wa;
        Wd[i] = Wg[o * 64 + 32 + c] - wa;
    }
    __syncthreads();
    if (tid < 2 * NPT) {
        const int n = tid % NPT;
        u64 xr[16]; ldrow(xr, xsrc + n * XS);
        if (tid < NPT) {
            #pragma unroll 4
            for (int o = 0; o < 32; ++o)
                U[n * 33 + o] = dot32s(xr, Wa + o * 32);
        } else {
            #pragma unroll 4
            for (int o = 0; o < 32; ++o)
                V[n * 33 + o] = dot32s(xr, Wd + o * 32);
        }
    }
    __syncthreads();
    if (tid < NPT) {
        const int n = tid;
        float m[32];
        #pragma unroll
        for (int o = 0; o < 32; ++o) m[o] = -3.4e38f;
        #pragma unroll 1
        for (int kk = 0; kk < KNN; ++kk) {
            const int j = idx[n * KNN + kk];
            const float* urow = U + j * 33;
            #pragma unroll
            for (int o = 0; o < 32; ++o) m[o] = fmaxf(m[o], urow[o]);
        }
        #pragma unroll
        for (int o = 0; o < 32; ++o)
            dest[n * XS + o] = lrelu(fmaf(sb[o], m[o] + V[n * 33 + o], tb[o]));
    }
    __syncthreads();
}

// ---------------------------------------------------------------------------
// Main fused kernel: one CTA per batch element, 256 threads, 2 CTAs/SM.
// smem map (floats): x0@0 x1@3600 x2@7200 x3@10800 | xx@14400 idx@14528(..15528)
// gbuf@15528 pbuf@16040 sts@16168 | scr@16552..26952   (no overlaps)
// ---------------------------------------------------------------------------
extern "C" __global__ void __launch_bounds__(NTHR, 2)
dgcnn_fused(Ptrs P, float* __restrict__ out)
{
    extern __shared__ float sm[];
    float* x0   = sm;
    float* x1   = sm + 3600;
    float* x2   = sm + 7200;
    float* x3   = sm + 10800;
    float* xx   = sm + 14400;
    int*   idx  = (int*)(sm + 14528);
    float* gbuf = sm + 15528;
    float* pbuf = sm + 16040;
    float* sts  = sm + 16168;
    float* scr  = sm + 16552;

    const int tid = threadIdx.x;
    const int b = blockIdx.x;

    for (int i = tid; i < 32 * 12; i += NTHR) {
        int g = i >> 5, c = i & 31, si = g >> 1;
        sts[i] = (g & 1) ? P.t[si][c] : P.s[si][c];
    }

    // ---- stage 0: x0 = lrelu(s0*(W0 @ obs_rows)+t0) ----
    for (int i = tid; i < 3000; i += NTHR) scr[i] = P.obs[b * 3000 + i];
    for (int i = tid; i < 960; i += NTHR)  scr[3072 + i] = P.W0[i];
    __syncthreads();
    for (int tt = tid; tt < 32 * NPT; tt += NTHR) {
        const int o = tt & 31, n = tt >> 5;
        const u64* wr = (const u64*)(scr + 3072 + o * 30);
        const u64* xr = (const u64*)(scr + n * 30);
        u64 s0 = 0, s1 = 0;
        #pragma unroll
        for (int i = 0; i < 14; i += 2) { fma2(s0, wr[i], xr[i]); fma2(s1, wr[i+1], xr[i+1]); }
        fma2(s0, wr[14], xr[14]);
        x0[n * XS + o] = lrelu(fmaf(sts[o], hsum(add2(s0, s1)), sts[32 + o]));
    }
    __syncthreads();

    // ---- 3x (kNN + EdgeConv) ----
    knn_stage(x0, xx, idx, scr, tid);
    edge_dual(x0, x1, idx, P.W1, P.W2, sts + 64, sts + 96, sts + 128, sts + 160,
              scr, x2, x3, tid);
    knn_stage(x1, xx, idx, scr, tid);
    edge_dual(x1, x2, idx, P.W3, P.W4, sts + 192, sts + 224, sts + 256, sts + 288,
              scr, x0, x3, tid);
    knn_stage(x2, xx, idx, scr, tid);
    edge_single(x2, x3, idx, P.W5, sts + 320, sts + 352, scr, tid);

    // ---- W6 (512x96) + global max -> g[512]; 2 outputs per thread, 4 accums ----
    #pragma unroll 1
    for (int rep = 0; rep < 2; ++rep) {
        const int o = tid + rep * NTHR;
        u64 w[48];
        const ulonglong2* wr = (const ulonglong2*)(P.W6 + o * 96);
        #pragma unroll
        for (int q = 0; q < 24; ++q) { ulonglong2 v = __ldg(wr + q); w[2*q] = v.x; w[2*q+1] = v.y; }
        float gmax = -3.4e38f;
        for (int n = 0; n < NPT; ++n) {
            u64 s0 = 0, s1 = 0, s2 = 0, s3 = 0;
            const ulonglong2* a  = (const ulonglong2*)(x1 + n * XS);
            const ulonglong2* bb = (const ulonglong2*)(x2 + n * XS);
            const ulonglong2* cc = (const ulonglong2*)(x3 + n * XS);
            #pragma unroll
            for (int i = 0; i < 8; ++i) { ulonglong2 v = a[i];  fma2(s0, w[2*i],    v.x); fma2(s1, w[2*i+1],    v.y); }
            #pragma unroll
            for (int i = 0; i < 8; ++i) { ulonglong2 v = bb[i]; fma2(s2, w[16+2*i], v.x); fma2(s3, w[16+2*i+1], v.y); }
            #pragma unroll
            for (int i = 0; i < 8; ++i) { ulonglong2 v = cc[i]; fma2(s0, w[32+2*i], v.x); fma2(s1, w[32+2*i+1], v.y); }
            gmax = fmaxf(gmax, hsum(add2(add2(s0, s2), add2(s1, s3))));
        }
        gbuf[o] = lrelu(fmaf(__ldg(P.s[6] + o), gmax, __ldg(P.t[6] + o)));
    }
    __syncthreads();

    // ---- p[o] = W7[o,:512] . g ----
    if (tid < 128) {
        const ulonglong2* wr = (const ulonglong2*)(P.W7 + tid * 608);
        const ulonglong2* gv = (const ulonglong2*)gbuf;
        u64 s0 = 0, s1 = 0, s2 = 0, s3 = 0;
        #pragma unroll 16
        for (int q = 0; q < 128; q += 2) {
            ulonglong2 w0 = __ldg(wr + q); ulonglong2 g0 = gv[q];
            ulonglong2 w1 = __ldg(wr + q + 1); ulonglong2 g1 = gv[q + 1];
            fma2(s0, w0.x, g0.x); fma2(s1, w0.y, g0.y);
            fma2(s2, w1.x, g1.x); fma2(s3, w1.y, g1.y);
        }
        pbuf[tid] = hsum(add2(add2(s0, s2), add2(s1, s3)));
    }
    __syncthreads();

    // ---- h2[n][o] = lrelu(s7*(p[o] + W7[o,512:608].xc[n]) + t7) ----
    // h2 rows 0..77 in scr, rows 78..99 in x0 (both stride 132)
    {
        const int o = tid & 127, nh = tid >> 7;
        u64 w[48];
        const ulonglong2* wr = (const ulonglong2*)(P.W7 + o * 608 + 512);
        #pragma unroll
        for (int q = 0; q < 24; ++q) { ulonglong2 v = __ldg(wr + q); w[2*q] = v.x; w[2*q+1] = v.y; }
        const float po = pbuf[o];
        const float so = __ldg(P.s[7] + o), to = __ldg(P.t[7] + o);
        for (int n = nh * 50; n < nh * 50 + 50; ++n) {
            u64 s0 = 0, s1 = 0, s2 = 0, s3 = 0;
            const ulonglong2* a  = (const ulonglong2*)(x1 + n * XS);
            const ulonglong2* bb = (const ulonglong2*)(x2 + n * XS);
            const ulonglong2* cc = (const ulonglong2*)(x3 + n * XS);
            #pragma unroll
            for (int i = 0; i < 8; ++i) { ulonglong2 v = a[i];  fma2(s0, w[2*i],    v.x); fma2(s1, w[2*i+1],    v.y); }
            #pragma unroll
            for (int i = 0; i < 8; ++i) { ulonglong2 v = bb[i]; fma2(s2, w[16+2*i], v.x); fma2(s3, w[16+2*i+1], v.y); }
            #pragma unroll
            for (int i = 0; i < 8; ++i) { ulonglong2 v = cc[i]; fma2(s0, w[32+2*i], v.x); fma2(s1, w[32+2*i+1], v.y); }
            float* hr = (n < 78 ? scr + n * 132 : x0 + (n - 78) * 132);
            hr[o] = lrelu(fmaf(so, po + hsum(add2(add2(s0, s2), add2(s1, s3))), to));
        }
    }
    __syncthreads();

    // ---- stage W8 (padded stride 132) into x1/x2 region (dead now) ----
    {
        float* w8p = x1;
        for (int i = tid; i < 4096; i += NTHR) {
            int o2 = i >> 7, c = i & 127;
            w8p[o2 * 132 + c] = P.W8[i];
        }
    }
    __syncthreads();

    // ---- W8 (32x128): y8 -> x3 region ----
    {
        const float* w8p = x1;
        float* y8 = x3;
        const float s8v = __ldg(P.s[8] + (tid & 31));
        const float t8v = __ldg(P.t[8] + (tid & 31));
        for (int tt = tid; tt < 32 * NPT; tt += NTHR) {
            const int o2 = tt & 31, n = tt >> 5;
            const float* hr = (n < 78 ? scr + n * 132 : x0 + (n - 78) * 132);
            const ulonglong2* wr = (const ulonglong2*)(w8p + o2 * 132);
            const ulonglong2* hv = (const ulonglong2*)hr;
            u64 s0 = 0, s1 = 0;
            #pragma unroll
            for (int q = 0; q < 32; ++q) {
                ulonglong2 wv = wr[q]; ulonglong2 h = hv[q];
                fma2(s0, wv.x, h.x); fma2(s1, wv.y, h.y);
            }
            y8[n * XS + o2] = lrelu(fmaf(s8v, hsum(add2(s0, s1)), t8v));
        }
    }
    __syncthreads();

    // ---- final head ----
    if (tid < NPT) {
        u64 w[16];
        const ulonglong2* wr = (const ulonglong2*)P.W9;
        #pragma unroll
        for (int q = 0; q < 8; ++q) { ulonglong2 v = __ldg(wr + q); w[2*q] = v.x; w[2*q+1] = v.y; }
        out[b * NPT + tid] = dot32s(w, x3 + tid * XS);
    }
}

extern "C" void kernel_launch(void* const* d_in, const int* in_sizes, int n_in,
                              void* d_out, int out_size)
{
    Ptrs P;
    P.obs = (const float*)d_in[0];
    P.W0 = (const float*)d_in[1];  P.W1 = (const float*)d_in[2];
    P.W2 = (const float*)d_in[3];  P.W3 = (const float*)d_in[4];
    P.W4 = (const float*)d_in[5];  P.W5 = (const float*)d_in[6];
    P.W6 = (const float*)d_in[7];  P.W7 = (const float*)d_in[8];
    P.W8 = (const float*)d_in[9];  P.W9 = (const float*)d_in[10];

    const bool separated = (n_in > 17 && in_sizes[17] == 512);
    for (int i = 0; i < 9; ++i) {
        if (separated) {
            P.s[i] = (const float*)d_in[11 + i];
            P.t[i] = (const float*)d_in[20 + i];
        } else {
            P.s[i] = (const float*)d_in[11 + 2 * i];
            P.t[i] = (const float*)d_in[12 + 2 * i];
        }
    }

    const int B = in_sizes[0] / 3000;
    const int smem_bytes = 26952 * 4;   // 105.3 KB -> 2 CTAs/SM
    cudaFuncSetAttribute(dgcnn_fused, cudaFuncAttributeMaxDynamicSharedMemorySize, smem_bytes);
    dgcnn_fused<<<B, NTHR, smem_bytes>>>(P, (float*)d_out);
}

// round 8
// speedup vs baseline: 2.7432x; 1.0719x over previous
#include <cuda_runtime.h>

#define NPT   100
#define KNN   10
#define XS    36
#define NTHR  256

typedef unsigned long long u64;

struct Ptrs {
    const float* obs;
    const float* W0; const float* W1; const float* W2; const float* W3; const float* W4;
    const float* W5; const float* W6; const float* W7; const float* W8; const float* W9;
    const float* s[9]; const float* t[9];
};

__device__ __forceinline__ float lrelu(float v) { return fmaxf(v, 0.2f * v); }

__device__ __forceinline__ u64 pack2(float lo, float hi) {
    u64 r; asm("mov.b64 %0,{%1,%2};" : "=l"(r) : "f"(lo), "f"(hi)); return r;
}
__device__ __forceinline__ void fma2(u64& d, u64 a, u64 b) {
    asm("fma.rn.f32x2 %0,%1,%2,%0;" : "+l"(d) : "l"(a), "l"(b));
}
__device__ __forceinline__ u64 add2(u64 a, u64 b) {
    u64 r; asm("add.rn.f32x2 %0,%1,%2;" : "=l"(r) : "l"(a), "l"(b)); return r;
}
__device__ __forceinline__ void unpack2(u64 v, float& a, float& b) {
    asm("mov.b64 {%0,%1},%2;" : "=f"(a), "=f"(b) : "l"(v));
}
__device__ __forceinline__ float hsum(u64 v) { float a, b; unpack2(v, a, b); return a + b; }
__device__ __forceinline__ u64 max2(u64 x, u64 y) {
    float xa, xb, ya, yb; unpack2(x, xa, xb); unpack2(y, ya, yb);
    return pack2(fmaxf(xa, ya), fmaxf(xb, yb));
}

__device__ __forceinline__ void ldrow(u64* r, const float* p) {
    const ulonglong2* q = (const ulonglong2*)p;
    #pragma unroll
    for (int i = 0; i < 8; ++i) { ulonglong2 v = q[i]; r[2*i] = v.x; r[2*i+1] = v.y; }
}
__device__ __forceinline__ float dot32s(const u64* a, const float* b) {
    const ulonglong2* q = (const ulonglong2*)b;
    u64 s0 = 0, s1 = 0;
    #pragma unroll
    for (int i = 0; i < 8; ++i) { ulonglong2 v = q[i]; fma2(s0, a[2*i], v.x); fma2(s1, a[2*i+1], v.y); }
    return hsum(add2(s0, s1));
}
__device__ __forceinline__ float dot32ss(const float* a, const float* b) {
    const ulonglong2* pa = (const ulonglong2*)a;
    const ulonglong2* pb = (const ulonglong2*)b;
    u64 s0 = 0, s1 = 0;
    #pragma unroll
    for (int i = 0; i < 8; ++i) {
        ulonglong2 va = pa[i], vb = pb[i];
        fma2(s0, va.x, vb.x); fma2(s1, va.y, vb.y);
    }
    return hsum(add2(s0, s1));
}

// ---------------------------------------------------------------------------
// kNN: 200 threads scan j-halves of 50 (2-way unrolled: two independent dot
// chains per iteration) -> per-half top-10; 100 threads merge.
// ---------------------------------------------------------------------------
__device__ void knn_stage(const float* __restrict__ xsrc, float* __restrict__ xx,
                          int* __restrict__ idx, float* __restrict__ scr, int tid)
{
    if (tid < NPT) {
        xx[tid] = dot32ss(xsrc + tid * XS, xsrc + tid * XS);
    }
    __syncthreads();
    float* vbuf = scr;                    // 200*10
    int*   ibuf = (int*)(scr + 2048);     // 200*10
    if (tid < 2 * NPT) {
        const int n = tid % NPT, h = tid / NPT;
        u64 xi[16]; ldrow(xi, xsrc + n * XS);
        const float nxi = xx[n];
        float v[KNN]; int id[KNN];
        #pragma unroll
        for (int p = 0; p < KNN; ++p) { v[p] = -3.4e38f; id[p] = 0; }
        #pragma unroll 1
        for (int j = h * 50; j < h * 50 + 50; j += 2) {
            // two independent dot chains
            const ulonglong2* ra = (const ulonglong2*)(xsrc + j * XS);
            const ulonglong2* rb = (const ulonglong2*)(xsrc + (j + 1) * XS);
            u64 a0 = 0, a1 = 0, b0 = 0, b1 = 0;
            #pragma unroll
            for (int i = 0; i < 8; ++i) {
                ulonglong2 va = ra[i], vb = rb[i];
                fma2(a0, xi[2*i], va.x); fma2(a1, xi[2*i+1], va.y);
                fma2(b0, xi[2*i], vb.x); fma2(b1, xi[2*i+1], vb.y);
            }
            const float da = 2.f * hsum(add2(a0, a1)) - nxi - xx[j];
            const float db = 2.f * hsum(add2(b0, b1)) - nxi - xx[j + 1];
            if (da > v[KNN - 1]) {
                float dv = da; int di = j;
                #pragma unroll
                for (int p = 0; p < KNN; ++p) {
                    if (dv > v[p]) {
                        float tv = v[p]; int ti = id[p];
                        v[p] = dv; id[p] = di; dv = tv; di = ti;
                    }
                }
            }
            if (db > v[KNN - 1]) {
                float dv = db; int di = j + 1;
                #pragma unroll
                for (int p = 0; p < KNN; ++p) {
                    if (dv > v[p]) {
                        float tv = v[p]; int ti = id[p];
                        v[p] = dv; id[p] = di; dv = tv; di = ti;
                    }
                }
            }
        }
        #pragma unroll
        for (int p = 0; p < KNN; ++p) { vbuf[tid * KNN + p] = v[p]; ibuf[tid * KNN + p] = id[p]; }
    }
    __syncthreads();
    if (tid < NPT) {
        const float* va = vbuf + tid * KNN; const float* vb = vbuf + (tid + NPT) * KNN;
        const int*   ia = ibuf + tid * KNN; const int*   ib = ibuf + (tid + NPT) * KNN;
        int pa = 0, pb = 0;
        #pragma unroll
        for (int p = 0; p < KNN; ++p) {
            bool ta = va[pa] >= vb[pb];
            idx[tid * KNN + p] = ta ? ia[pa] : ib[pb];
            if (ta) ++pa; else ++pb;
        }
    }
    __syncthreads();
}

// ---------------------------------------------------------------------------
// Dual-conv EdgeConv with U/V factoring + neighbor-batched second conv.
// ---------------------------------------------------------------------------
__device__ void edge_dual(const float* __restrict__ xsrc, float* __restrict__ dest,
                          const int* __restrict__ idx,
                          const float* __restrict__ Wg, const float* __restrict__ Wbg,
                          const float* __restrict__ sa, const float* __restrict__ ta,
                          const float* __restrict__ sb, const float* __restrict__ tb,
                          float* __restrict__ scr,
                          float* __restrict__ pmA, float* __restrict__ pmB, int tid)
{
    float* Wa  = scr;             // 1024
    float* Wd  = scr + 1024;      // 1024
    float* Wbt = scr + 2048;      // 1024
    float* U   = scr + 3072;      // 100*34 = 3400
    float* V   = scr + 6472;      // 100*34 = 3400
    for (int i = tid; i < 1024; i += NTHR) {
        int o = i >> 5, c = i & 31;
        float wa = Wg[o * 64 + c];
        Wa[i] = wa;
        Wd[i] = Wg[o * 64 + 32 + c] - wa;
        Wbt[c * 32 + o] = Wbg[i];
    }
    __syncthreads();

    // phase 1: per-point U'/V'
    if (tid < 2 * NPT) {
        const int n = tid % NPT;
        u64 xr[16]; ldrow(xr, xsrc + n * XS);
        if (tid < NPT) {
            #pragma unroll 4
            for (int o = 0; o < 32; ++o)
                U[n * 34 + o] = sa[o] * dot32s(xr, Wa + o * 32);
        } else {
            #pragma unroll 4
            for (int o = 0; o < 32; ++o)
                V[n * 34 + o] = fmaf(sa[o], dot32s(xr, Wd + o * 32), ta[o]);
        }
    }
    __syncthreads();

    // phase 2: neighbor-batched second conv + running max
    if (tid < 2 * NPT) {
        const int n = tid % NPT, kh = tid / NPT;
        const int base = n * KNN + kh * 5;
        const int j0 = idx[base], j1 = idx[base + 1], j2 = idx[base + 2];
        const int j3 = idx[base + 3], j4 = idx[base + 4];
        const u64* vq = (const u64*)(V + n * 34);
        const u64* ua = (const u64*)(U + j0 * 34);
        const u64* ub = (const u64*)(U + j1 * 34);
        const u64* uc = (const u64*)(U + j2 * 34);
        const u64* ud = (const u64*)(U + j3 * 34);
        const u64* ue = (const u64*)(U + j4 * 34);
        float* pr = (kh == 0 ? pmA : pmB) + n * XS;
        #pragma unroll 1
        for (int half = 0; half < 2; ++half) {
            const float* WbtH = Wbt + half * 16;
            u64 m[8];
            #pragma unroll
            for (int i = 0; i < 8; ++i) m[i] = pack2(-3.4e38f, -3.4e38f);
            // group of 3 neighbors (j0,j1,j2)
            {
                u64 za[8], zb[8], zc[8];
                #pragma unroll
                for (int i = 0; i < 8; ++i) { za[i] = 0; zb[i] = 0; zc[i] = 0; }
                #pragma unroll 4
                for (int p = 0; p < 16; ++p) {
                    const u64 vv = vq[p];
                    float a0, a1, b0, b1, c0, c1;
                    unpack2(add2(ua[p], vv), a0, a1);
                    unpack2(add2(ub[p], vv), b0, b1);
                    unpack2(add2(uc[p], vv), c0, c1);
                    a0 = lrelu(a0); a1 = lrelu(a1);
                    b0 = lrelu(b0); b1 = lrelu(b1);
                    c0 = lrelu(c0); c1 = lrelu(c1);
                    const u64 ya0 = pack2(a0, a0), ya1 = pack2(a1, a1);
                    const u64 yb0 = pack2(b0, b0), yb1 = pack2(b1, b1);
                    const u64 yc0 = pack2(c0, c0), yc1 = pack2(c1, c1);
                    const ulonglong2* wA = (const ulonglong2*)(WbtH + (2 * p) * 32);
                    const ulonglong2* wB = (const ulonglong2*)(WbtH + (2 * p + 1) * 32);
                    #pragma unroll
                    for (int q = 0; q < 4; ++q) {
                        ulonglong2 wa2 = wA[q], wb2 = wB[q];
                        fma2(za[2*q],   ya0, wa2.x); fma2(za[2*q+1], ya0, wa2.y);
                        fma2(za[2*q],   ya1, wb2.x); fma2(za[2*q+1], ya1, wb2.y);
                        fma2(zb[2*q],   yb0, wa2.x); fma2(zb[2*q+1], yb0, wa2.y);
                        fma2(zb[2*q],   yb1, wb2.x); fma2(zb[2*q+1], yb1, wb2.y);
                        fma2(zc[2*q],   yc0, wa2.x); fma2(zc[2*q+1], yc0, wa2.y);
                        fma2(zc[2*q],   yc1, wb2.x); fma2(zc[2*q+1], yc1, wb2.y);
                    }
                }
                #pragma unroll
                for (int i = 0; i < 8; ++i) m[i] = max2(m[i], max2(za[i], max2(zb[i], zc[i])));
            }
            // group of 2 neighbors (j3,j4)
            {
                u64 za[8], zb[8];
                #pragma unroll
                for (int i = 0; i < 8; ++i) { za[i] = 0; zb[i] = 0; }
                #pragma unroll 4
                for (int p = 0; p < 16; ++p) {
                    const u64 vv = vq[p];
                    float a0, a1, b0, b1;
                    unpack2(add2(ud[p], vv), a0, a1);
                    unpack2(add2(ue[p], vv), b0, b1);
                    a0 = lrelu(a0); a1 = lrelu(a1);
                    b0 = lrelu(b0); b1 = lrelu(b1);
                    const u64 ya0 = pack2(a0, a0), ya1 = pack2(a1, a1);
                    const u64 yb0 = pack2(b0, b0), yb1 = pack2(b1, b1);
                    const ulonglong2* wA = (const ulonglong2*)(WbtH + (2 * p) * 32);
                    const ulonglong2* wB = (const ulonglong2*)(WbtH + (2 * p + 1) * 32);
                    #pragma unroll
                    for (int q = 0; q < 4; ++q) {
                        ulonglong2 wa2 = wA[q], wb2 = wB[q];
                        fma2(za[2*q],   ya0, wa2.x); fma2(za[2*q+1], ya0, wa2.y);
                        fma2(za[2*q],   ya1, wb2.x); fma2(za[2*q+1], ya1, wb2.y);
                        fma2(zb[2*q],   yb0, wa2.x); fma2(zb[2*q+1], yb0, wa2.y);
                        fma2(zb[2*q],   yb1, wb2.x); fma2(zb[2*q+1], yb1, wb2.y);
                    }
                }
                #pragma unroll
                for (int i = 0; i < 8; ++i) m[i] = max2(m[i], max2(za[i], zb[i]));
            }
            u64* prq = (u64*)(pr + half * 16);
            #pragma unroll
            for (int i = 0; i < 8; ++i) prq[i] = m[i];
        }
    }
    __syncthreads();
    for (int i = tid; i < 32 * NPT; i += NTHR) {
        const int n = i >> 5, o = i & 31;
        float mv = fmaxf(pmA[n * XS + o], pmB[n * XS + o]);
        dest[n * XS + o] = lrelu(fmaf(sb[o], mv, tb[o]));
    }
    __syncthreads();
}

// ---------------------------------------------------------------------------
// Single-conv EdgeConv with U/V factoring.
// ---------------------------------------------------------------------------
__device__ void edge_single(const float* __restrict__ xsrc, float* __restrict__ dest,
                            const int* __restrict__ idx,
                            const float* __restrict__ Wg,
                            const float* __restrict__ sb, const float* __restrict__ tb,
                            float* __restrict__ scr, int tid)
{
    float* Wa = scr;             // 1024
    float* Wd = scr + 1024;      // 1024
    float* U  = scr + 3072;      // 100*33
    float* V  = scr + 6472;      // 100*33
    for (int i = tid; i < 1024; i += NTHR) {
        int o = i >> 5, c = i & 31;
        float wa = Wg[o * 64 + c];
        Wa[i] = wa;
        Wd[i] = Wg[o * 64 + 32 + c] - wa;
    }
    __syncthreads();
    if (tid < 2 * NPT) {
        const int n = tid % NPT;
        u64 xr[16]; ldrow(xr, xsrc + n * XS);
        if (tid < NPT) {
            #pragma unroll 4
            for (int o = 0; o < 32; ++o)
                U[n * 33 + o] = dot32s(xr, Wa + o * 32);
        } else {
            #pragma unroll 4
            for (int o = 0; o < 32; ++o)
                V[n * 33 + o] = dot32s(xr, Wd + o * 32);
        }
    }
    __syncthreads();
    if (tid < NPT) {
        const int n = tid;
        float m[32];
        #pragma unroll
        for (int o = 0; o < 32; ++o) m[o] = -3.4e38f;
        #pragma unroll 1
        for (int kk = 0; kk < KNN; ++kk) {
            const int j = idx[n * KNN + kk];
            const float* urow = U + j * 33;
            #pragma unroll
            for (int o = 0; o < 32; ++o) m[o] = fmaxf(m[o], urow[o]);
        }
        #pragma unroll
        for (int o = 0; o < 32; ++o)
            dest[n * XS + o] = lrelu(fmaf(sb[o], m[o] + V[n * 33 + o], tb[o]));
    }
    __syncthreads();
}

// ---------------------------------------------------------------------------
// Main fused kernel: one CTA per batch element, 256 threads, 2 CTAs/SM.
// smem map (floats): x0@0 x1@3600 x2@7200 x3@10800 | xx@14400 idx@14528(..15528)
// gbuf@15528 pbuf@16040 sts@16168 | scr@16552..26952   (no overlaps)
// ---------------------------------------------------------------------------
extern "C" __global__ void __launch_bounds__(NTHR, 2)
dgcnn_fused(Ptrs P, float* __restrict__ out)
{
    extern __shared__ float sm[];
    float* x0   = sm;
    float* x1   = sm + 3600;
    float* x2   = sm + 7200;
    float* x3   = sm + 10800;
    float* xx   = sm + 14400;
    int*   idx  = (int*)(sm + 14528);
    float* gbuf = sm + 15528;
    float* pbuf = sm + 16040;
    float* sts  = sm + 16168;
    float* scr  = sm + 16552;

    const int tid = threadIdx.x;
    const int b = blockIdx.x;

    for (int i = tid; i < 32 * 12; i += NTHR) {
        int g = i >> 5, c = i & 31, si = g >> 1;
        sts[i] = (g & 1) ? P.t[si][c] : P.s[si][c];
    }

    // ---- stage 0: x0 = lrelu(s0*(W0 @ obs_rows)+t0) ----
    for (int i = tid; i < 3000; i += NTHR) scr[i] = P.obs[b * 3000 + i];
    for (int i = tid; i < 960; i += NTHR)  scr[3072 + i] = P.W0[i];
    __syncthreads();
    for (int tt = tid; tt < 32 * NPT; tt += NTHR) {
        const int o = tt & 31, n = tt >> 5;
        const u64* wr = (const u64*)(scr + 3072 + o * 30);
        const u64* xr = (const u64*)(scr + n * 30);
        u64 s0 = 0, s1 = 0;
        #pragma unroll
        for (int i = 0; i < 14; i += 2) { fma2(s0, wr[i], xr[i]); fma2(s1, wr[i+1], xr[i+1]); }
        fma2(s0, wr[14], xr[14]);
        x0[n * XS + o] = lrelu(fmaf(sts[o], hsum(add2(s0, s1)), sts[32 + o]));
    }
    __syncthreads();

    // ---- 3x (kNN + EdgeConv) ----
    knn_stage(x0, xx, idx, scr, tid);
    edge_dual(x0, x1, idx, P.W1, P.W2, sts + 64, sts + 96, sts + 128, sts + 160,
              scr, x2, x3, tid);
    knn_stage(x1, xx, idx, scr, tid);
    edge_dual(x1, x2, idx, P.W3, P.W4, sts + 192, sts + 224, sts + 256, sts + 288,
              scr, x0, x3, tid);
    knn_stage(x2, xx, idx, scr, tid);
    edge_single(x2, x3, idx, P.W5, sts + 320, sts + 352, scr, tid);

    // ---- W6 (512x96) + global max -> g[512]; 2 outputs/thread, 2-n unroll ----
    #pragma unroll 1
    for (int rep = 0; rep < 2; ++rep) {
        const int o = tid + rep * NTHR;
        u64 w[48];
        const ulonglong2* wr = (const ulonglong2*)(P.W6 + o * 96);
        #pragma unroll
        for (int q = 0; q < 24; ++q) { ulonglong2 v = __ldg(wr + q); w[2*q] = v.x; w[2*q+1] = v.y; }
        float gmax = -3.4e38f;
        #pragma unroll 1
        for (int n = 0; n < NPT; n += 2) {
            u64 s0 = 0, s1 = 0, s2 = 0, s3 = 0;
            const ulonglong2* a0p = (const ulonglong2*)(x1 + n * XS);
            const ulonglong2* b0p = (const ulonglong2*)(x2 + n * XS);
            const ulonglong2* c0p = (const ulonglong2*)(x3 + n * XS);
            const ulonglong2* a1p = (const ulonglong2*)(x1 + (n + 1) * XS);
            const ulonglong2* b1p = (const ulonglong2*)(x2 + (n + 1) * XS);
            const ulonglong2* c1p = (const ulonglong2*)(x3 + (n + 1) * XS);
            #pragma unroll
            for (int i = 0; i < 8; ++i) {
                ulonglong2 v0 = a0p[i], v1 = a1p[i];
                fma2(s0, w[2*i],   v0.x); fma2(s1, w[2*i+1],   v0.y);
                fma2(s2, w[2*i],   v1.x); fma2(s3, w[2*i+1],   v1.y);
            }
            #pragma unroll
            for (int i = 0; i < 8; ++i) {
                ulonglong2 v0 = b0p[i], v1 = b1p[i];
                fma2(s0, w[16+2*i], v0.x); fma2(s1, w[16+2*i+1], v0.y);
                fma2(s2, w[16+2*i], v1.x); fma2(s3, w[16+2*i+1], v1.y);
            }
            #pragma unroll
            for (int i = 0; i < 8; ++i) {
                ulonglong2 v0 = c0p[i], v1 = c1p[i];
                fma2(s0, w[32+2*i], v0.x); fma2(s1, w[32+2*i+1], v0.y);
                fma2(s2, w[32+2*i], v1.x); fma2(s3, w[32+2*i+1], v1.y);
            }
            gmax = fmaxf(gmax, fmaxf(hsum(add2(s0, s1)), hsum(add2(s2, s3))));
        }
        gbuf[o] = lrelu(fmaf(__ldg(P.s[6] + o), gmax, __ldg(P.t[6] + o)));
    }
    __syncthreads();

    // ---- p[o] = W7[o,:512] . g ----
    if (tid < 128) {
        const ulonglong2* wr = (const ulonglong2*)(P.W7 + tid * 608);
        const ulonglong2* gv = (const ulonglong2*)gbuf;
        u64 s0 = 0, s1 = 0, s2 = 0, s3 = 0;
        #pragma unroll 16
        for (int q = 0; q < 128; q += 2) {
            ulonglong2 w0 = __ldg(wr + q); ulonglong2 g0 = gv[q];
            ulonglong2 w1 = __ldg(wr + q + 1); ulonglong2 g1 = gv[q + 1];
            fma2(s0, w0.x, g0.x); fma2(s1, w0.y, g0.y);
            fma2(s2, w1.x, g1.x); fma2(s3, w1.y, g1.y);
        }
        pbuf[tid] = hsum(add2(add2(s0, s2), add2(s1, s3)));
    }
    __syncthreads();

    // ---- h2[n][o] = lrelu(s7*(p[o] + W7[o,512:608].xc[n]) + t7), 2-n unroll ----
    // h2 rows 0..77 in scr, rows 78..99 in x0 (both stride 132)
    {
        const int o = tid & 127, nh = tid >> 7;
        u64 w[48];
        const ulonglong2* wr = (const ulonglong2*)(P.W7 + o * 608 + 512);
        #pragma unroll
        for (int q = 0; q < 24; ++q) { ulonglong2 v = __ldg(wr + q); w[2*q] = v.x; w[2*q+1] = v.y; }
        const float po = pbuf[o];
        const float so = __ldg(P.s[7] + o), to = __ldg(P.t[7] + o);
        #pragma unroll 1
        for (int n = nh * 50; n < nh * 50 + 50; n += 2) {
            u64 s0 = 0, s1 = 0, s2 = 0, s3 = 0;
            const ulonglong2* a0p = (const ulonglong2*)(x1 + n * XS);
            const ulonglong2* b0p = (const ulonglong2*)(x2 + n * XS);
            const ulonglong2* c0p = (const ulonglong2*)(x3 + n * XS);
            const ulonglong2* a1p = (const ulonglong2*)(x1 + (n + 1) * XS);
            const ulonglong2* b1p = (const ulonglong2*)(x2 + (n + 1) * XS);
            const ulonglong2* c1p = (const ulonglong2*)(x3 + (n + 1) * XS);
            #pragma unroll
            for (int i = 0; i < 8; ++i) {
                ulonglong2 v0 = a0p[i], v1 = a1p[i];
                fma2(s0, w[2*i],   v0.x); fma2(s1, w[2*i+1],   v0.y);
                fma2(s2, w[2*i],   v1.x); fma2(s3, w[2*i+1],   v1.y);
            }
            #pragma unroll
            for (int i = 0; i < 8; ++i) {
                ulonglong2 v0 = b0p[i], v1 = b1p[i];
                fma2(s0, w[16+2*i], v0.x); fma2(s1, w[16+2*i+1], v0.y);
                fma2(s2, w[16+2*i], v1.x); fma2(s3, w[16+2*i+1], v1.y);
            }
            #pragma unroll
            for (int i = 0; i < 8; ++i) {
                ulonglong2 v0 = c0p[i], v1 = c1p[i];
                fma2(s0, w[32+2*i], v0.x); fma2(s1, w[32+2*i+1], v0.y);
                fma2(s2, w[32+2*i], v1.x); fma2(s3, w[32+2*i+1], v1.y);
            }
            float* hr0 = (n < 78 ? scr + n * 132 : x0 + (n - 78) * 132);
            float* hr1 = (n + 1 < 78 ? scr + (n + 1) * 132 : x0 + (n + 1 - 78) * 132);
            hr0[o] = lrelu(fmaf(so, po + hsum(add2(s0, s1)), to));
            hr1[o] = lrelu(fmaf(so, po + hsum(add2(s2, s3)), to));
        }
    }
    __syncthreads();

    // ---- stage W8 (padded stride 132) into x1/x2 region (dead now) ----
    {
        float* w8p = x1;
        for (int i = tid; i < 4096; i += NTHR) {
            int o2 = i >> 7, c = i & 127;
            w8p[o2 * 132 + c] = P.W8[i];
        }
    }
    __syncthreads();

    // ---- W8 (32x128) fused with head: warp owns n (lane = o2), shuffle-reduce ----
    {
        const float* w8p = x1;
        const int lane = tid & 31;
        const float s8v = __ldg(P.s[8] + lane);
        const float t8v = __ldg(P.t[8] + lane);
        const float w9l = __ldg(P.W9 + lane);
        const ulonglong2* wr = (const ulonglong2*)(w8p + lane * 132);
        for (int tt = tid; tt < 32 * NPT; tt += NTHR) {
            const int n = tt >> 5;
            const float* hr = (n < 78 ? scr + n * 132 : x0 + (n - 78) * 132);
            const ulonglong2* hv = (const ulonglong2*)hr;
            u64 s0 = 0, s1 = 0;
            #pragma unroll
            for (int q = 0; q < 32; ++q) {
                ulonglong2 wv = wr[q]; ulonglong2 h = hv[q];
                fma2(s0, wv.x, h.x); fma2(s1, wv.y, h.y);
            }
            const float y8v = lrelu(fmaf(s8v, hsum(add2(s0, s1)), t8v));
            float r = y8v * w9l;
            r += __shfl_xor_sync(0xffffffffu, r, 16);
            r += __shfl_xor_sync(0xffffffffu, r, 8);
            r += __shfl_xor_sync(0xffffffffu, r, 4);
            r += __shfl_xor_sync(0xffffffffu, r, 2);
            r += __shfl_xor_sync(0xffffffffu, r, 1);
            if (lane == 0) out[b * NPT + n] = r;
        }
    }
}

extern "C" void kernel_launch(void* const* d_in, const int* in_sizes, int n_in,
                              void* d_out, int out_size)
{
    Ptrs P;
    P.obs = (const float*)d_in[0];
    P.W0 = (const float*)d_in[1];  P.W1 = (const float*)d_in[2];
    P.W2 = (const float*)d_in[3];  P.W3 = (const float*)d_in[4];
    P.W4 = (const float*)d_in[5];  P.W5 = (const float*)d_in[6];
    P.W6 = (const float*)d_in[7];  P.W7 = (const float*)d_in[8];
    P.W8 = (const float*)d_in[9];  P.W9 = (const float*)d_in[10];

    const bool separated = (n_in > 17 && in_sizes[17] == 512);
    for (int i = 0; i < 9; ++i) {
        if (separated) {
            P.s[i] = (const float*)d_in[11 + i];
            P.t[i] = (const float*)d_in[20 + i];
        } else {
            P.s[i] = (const float*)d_in[11 + 2 * i];
            P.t[i] = (const float*)d_in[12 + 2 * i];
        }
    }

    const int B = in_sizes[0] / 3000;
    const int smem_bytes = 26952 * 4;   // 105.3 KB -> 2 CTAs/SM
    cudaFuncSetAttribute(dgcnn_fused, cudaFuncAttributeMaxDynamicSharedMemorySize, smem_bytes);
    dgcnn_fused<<<B, NTHR, smem_bytes>>>(P, (float*)d_out);
}